// round 2
// baseline (speedup 1.0000x reference)
#include <cuda_runtime.h>
#include <cuda_bf16.h>
#include <math.h>

// Problem constants
#define BATCH   256
#define NEI     128
#define NRELS   5000
#define NSUP    32
#define DIM     128
#define TOPK    64
#define NCAND   8192

// d_out (float32) segment offsets (flatten+concat of the 5 reference outputs)
#define OFF_TN  0           // tree_node      [256,3,64]
#define OFF_TE  49152       // tree_emb_all   [256,3,64,128]
#define OFF_PI  6340608     // parent_index   [256,3,64]
#define OFF_PN  6389760     // parent_node    [256,3,64]
#define OFF_AR  6438912     // aim_rel_all    [256,3,64]

typedef unsigned long long ull;
typedef unsigned int u32;

// ---------------- device scratch (static: no allocation allowed) -------------
__device__ float g_best[NRELS];               // max-over-support score per relation
__device__ float g_relgi[NRELS * 384];        // rel_emb @ W_ih^T + b_ih
__device__ float g_wT[2][128 * 384];          // [0]=W_ih^T, [1]=W_hh^T  (k-major)
__device__ int   g_e[3][BATCH * TOPK];
__device__ int   g_r[3][BATCH * TOPK];
__device__ int   g_p[3][BATCH * TOPK];

// ---------------- f32x2 packed math helpers ----------------------------------
__device__ __forceinline__ ull f2pack(float lo, float hi) {
    ull d; asm("mov.b64 %0, {%1, %2};" : "=l"(d) : "f"(lo), "f"(hi)); return d;
}
__device__ __forceinline__ ull f2fma(ull a, ull b, ull c) {
    ull d; asm("fma.rn.f32x2 %0, %1, %2, %3;" : "=l"(d) : "l"(a), "l"(b), "l"(c)); return d;
}
__device__ __forceinline__ u32 ord32(float s) {
    u32 u = __float_as_uint(s);
    return (u & 0x80000000u) ? ~u : (u | 0x80000000u);
}

// ---------------- prep: transpose weights + best[] ----------------------------
__global__ void prep_best_kernel(const float* __restrict__ wih, const float* __restrict__ whh,
                                 const float* __restrict__ cosm, const int* __restrict__ sup) {
    const int bid = blockIdx.x;
    const int tid = threadIdx.x;
    if (bid < 192) {
        int idx = bid * 256 + tid;
        if (idx < 384 * 128) {
            int j = idx / 128, k = idx % 128;
            g_wT[0][k * 384 + j] = wih[idx];
            g_wT[1][k * 384 + j] = whh[idx];
        }
    } else {
        __shared__ int ss[NSUP];
        if (tid < NSUP) ss[tid] = sup[tid];
        __syncthreads();
        int r = (bid - 192) * 256 + tid;
        if (r < NRELS) {
            float m = -3.4e38f;
            #pragma unroll
            for (int s = 0; s < NSUP; ++s)
                m = fmaxf(m, cosm[(long long)ss[s] * NRELS + r]);
            g_best[r] = m;
        }
    }
}

// ---------------- rel_gi = rel_emb @ W_ih^T + b_ih  (FFMA2) -------------------
#define SH 20   // padded transpose row stride (floats); 20*4=80B keeps 16B align
__global__ void __launch_bounds__(384) relgi_kernel(const float* __restrict__ rel_emb,
                                                    const float* __restrict__ b_ih) {
    const int rb = blockIdx.x * 16;
    const int tid = threadIdx.x;
    __shared__ float s_f[128 * SH];   // [d][n] pair-packed along n
    for (int idx = tid; idx < 16 * 128; idx += 384) {
        int n = idx >> 7, d = idx & 127;
        int r = rb + n;
        s_f[d * SH + n] = (r < NRELS) ? rel_emb[r * 128 + d] : 0.f;
    }
    __syncthreads();
    const int j = tid;
    const float bj = b_ih[j];
    ull acc[8];
    ull bj2 = f2pack(bj, bj);
    #pragma unroll
    for (int m = 0; m < 8; ++m) acc[m] = bj2;
    const float* wt = g_wT[0];
    #pragma unroll 4
    for (int k = 0; k < 128; ++k) {
        float w = __ldg(&wt[k * 384 + j]);
        ull wd = f2pack(w, w);
        const ulonglong2* row = (const ulonglong2*)&s_f[k * SH];
        ulonglong2 r0 = row[0], r1 = row[1], r2 = row[2], r3 = row[3];
        acc[0] = f2fma(wd, r0.x, acc[0]); acc[1] = f2fma(wd, r0.y, acc[1]);
        acc[2] = f2fma(wd, r1.x, acc[2]); acc[3] = f2fma(wd, r1.y, acc[3]);
        acc[4] = f2fma(wd, r2.x, acc[4]); acc[5] = f2fma(wd, r2.y, acc[5]);
        acc[6] = f2fma(wd, r3.x, acc[6]); acc[7] = f2fma(wd, r3.y, acc[7]);
    }
    #pragma unroll
    for (int m = 0; m < 8; ++m) {
        float2 v = *(float2*)&acc[m];
        int r0i = rb + 2 * m, r1i = rb + 2 * m + 1;
        if (r0i < NRELS) g_relgi[r0i * 384 + j] = v.x;
        if (r1i < NRELS) g_relgi[r1i * 384 + j] = v.y;
    }
}

// ---------------- expand step 0: 128 candidates, rank-based top-64 ------------
__global__ void expand0_kernel(const int2* __restrict__ edge,
                               const int* __restrict__ query_head,
                               float* __restrict__ out) {
    __shared__ ull keys[128];
    __shared__ int s_ent;
    const int b = blockIdx.x;
    const int i = threadIdx.x;
    if (i == 0) s_ent = query_head[b];
    __syncthreads();
    const int ent = s_ent;
    int2 pr = __ldg(&edge[(long long)ent * NEI + i]);
    ull mykey = ((ull)ord32(g_best[pr.y]) << 32) | (u32)(127 - i);
    keys[i] = mykey;
    __syncthreads();
    int rank = 0;
    #pragma unroll 8
    for (int t = 0; t < 128; ++t) rank += (keys[t] > mykey);
    if (rank < TOPK) {
        int j = rank;
        int gidx = b * TOPK + j;
        g_e[0][gidx] = pr.x;
        g_r[0][gidx] = pr.y;
        g_p[0][gidx] = 0;
        out[OFF_TN + b * 192 + j] = (float)pr.x;
        out[OFF_PN + b * 192 + j] = (float)ent;
        out[OFF_PI + b * 192 + 128 + j] = (float)j;
    }
}

// ---------------- expand steps 1/2: radix-select top-64 of 8192 ---------------
__global__ void __launch_bounds__(512) expand_big_kernel(const int2* __restrict__ edge,
                                                         float* __restrict__ out, int step) {
    __shared__ u32 su[NCAND];         // 32KB ordered score keys
    __shared__ u32 hist[8][256];      // 8KB per-warp-pair histograms
    __shared__ u32 tot[257];          // suffix sums (+pad)
    __shared__ ull wkeys[TOPK];
    __shared__ int s_cur[TOPK];
    __shared__ u32 s_digit, s_gt, s_neq, s_wcount;

    const int b = blockIdx.x;
    const int tid = threadIdx.x;
    const int wp = (tid >> 5) & 7;

    if (tid < TOPK) s_cur[tid] = g_e[step - 1][b * TOPK + tid];
    if (tid == 0) { s_neq = 0; s_wcount = 0; }
    __syncthreads();

    // Phase A: score all candidates
    #pragma unroll
    for (int m = 0; m < 16; ++m) {
        int i = tid + m * 512;
        int c = i >> 7, n = i & 127;
        int2 pr = __ldg(&edge[(long long)s_cur[c] * NEI + n]);
        su[i] = ord32(g_best[pr.y]);
    }
    __syncthreads();

    // Phase B: 4-pass radix select (8-bit digits, MSB first)
    u32 prefix = 0, maskhi = 0, krem = TOPK;
    #pragma unroll
    for (int pass = 0; pass < 4; ++pass) {
        const int shift = 24 - 8 * pass;
        // zero hists
        for (int z = tid; z < 8 * 256; z += 512) ((u32*)hist)[z] = 0;
        __syncthreads();
        #pragma unroll
        for (int m = 0; m < 16; ++m) {
            int i = tid + m * 512;
            u32 u = su[i];
            if ((u & maskhi) == prefix)
                atomicAdd(&hist[wp][(u >> shift) & 255], 1u);
        }
        __syncthreads();
        if (tid < 256) {
            u32 s = 0;
            #pragma unroll
            for (int w = 0; w < 8; ++w) s += hist[w][tid];
            tot[tid] = s;
            if (tid == 0) tot[256] = 0;
        }
        __syncthreads();
        // inclusive suffix sum over 256 bins
        #pragma unroll
        for (int st = 1; st < 256; st <<= 1) {
            u32 v = 0;
            if (tid < 256) v = tot[tid] + ((tid + st < 256) ? tot[tid + st] : 0u);
            __syncthreads();
            if (tid < 256) tot[tid] = v;
            __syncthreads();
        }
        if (tid < 256) {
            u32 ge = tot[tid], gt = tot[tid + 1];
            if (ge >= krem && gt < krem) { s_digit = (u32)tid; s_gt = gt; }
        }
        __syncthreads();
        prefix |= s_digit << shift;
        maskhi |= 0xFFu << shift;
        krem -= s_gt;
        __syncthreads();
    }
    const u32 T = prefix;
    const u32 keq = krem;

    // count ties at T
    {
        u32 cnt = 0;
        #pragma unroll
        for (int m = 0; m < 16; ++m) cnt += (su[tid + m * 512] == T);
        if (cnt) atomicAdd(&s_neq, cnt);
    }
    __syncthreads();
    const u32 neq = s_neq;

    // Phase C: compact winners (unordered)
    #pragma unroll
    for (int m = 0; m < 16; ++m) {
        int i = tid + m * 512;
        u32 u = su[i];
        bool win = false;
        if (u > T) win = true;
        else if (u == T) {
            if (neq == keq) win = true;
            else {
                u32 c = 0;
                for (int jj = 0; jj < i; ++jj) c += (su[jj] == T);
                win = (c < keq);
            }
        }
        if (win) {
            u32 p = atomicAdd(&s_wcount, 1u);
            wkeys[p] = ((ull)u << 32) | (u32)(NCAND - 1 - i);
        }
    }
    __syncthreads();

    // Phase D: rank winners (value desc, index asc) and emit
    if (tid < TOPK) {
        ull mykey = wkeys[tid];
        int rank = 0;
        #pragma unroll 8
        for (int t = 0; t < TOPK; ++t) rank += (wkeys[t] > mykey);
        int i = NCAND - 1 - (int)(u32)(mykey & 0xffffffffu);
        int c = i >> 7, n = i & 127;
        int ent = s_cur[c];
        int2 pr = __ldg(&edge[(long long)ent * NEI + n]);
        int j = rank;
        int gidx = b * TOPK + j;
        g_e[step][gidx] = pr.x;
        g_r[step][gidx] = pr.y;
        g_p[step][gidx] = c;
        out[OFF_TN + b * 192 + step * 64 + j] = (float)pr.x;
        if (step == 1) {
            out[OFF_PI + b * 192 + j]       = (float)c;
            out[OFF_PN + b * 192 + 64 + j]  = (float)g_e[0][b * TOPK + c];
            out[OFF_AR + b * 192 + j]       = (float)g_r[0][b * TOPK + c];
        } else {
            out[OFF_PI + b * 192 + 64 + j]  = (float)c;
            out[OFF_PN + b * 192 + 128 + j] = (float)g_e[1][b * TOPK + c];
            out[OFF_AR + b * 192 + 64 + j]  = (float)g_r[1][b * TOPK + c];
            out[OFF_AR + b * 192 + 128 + j] = (float)pr.y;
        }
    }
}

// ---------------- GRU step 1 (h = 0 => gh = b_hh, pure elementwise) ----------
__global__ void gru1_kernel(const float* __restrict__ b_hh, float* __restrict__ out) {
    const int b = blockIdx.x;
    for (int idx = threadIdx.x; idx < TOPK * 128; idx += blockDim.x) {
        int k = idx >> 7, d = idx & 127;
        int r = g_r[0][b * TOPK + k];
        const float* gi = &g_relgi[r * 384];
        float hr = b_hh[d], hz = b_hh[128 + d], hn = b_hh[256 + d];
        float rg = 1.f / (1.f + expf(-(gi[d] + hr)));
        float z  = 1.f / (1.f + expf(-(gi[128 + d] + hz)));
        float nn = tanhf(gi[256 + d] + rg * hn);
        out[OFF_TE + ((b * 3 + 0) * 64 + k) * 128 + d] = (1.f - z) * nn;
    }
}

// ---------------- GRU steps 2/3: gh = h_parent @ W_hh^T + b_hh  (FFMA2) ------
__global__ void __launch_bounds__(384) gru23_kernel(const float* __restrict__ b_hh,
                                                    float* __restrict__ out, int step) {
    const int b = blockIdx.y;
    const int kb = blockIdx.x * 16;
    const int tid = threadIdx.x;
    __shared__ float s_f[128 * SH];   // h_parent transposed: s_f[d*SH+n] = h[n][d]
    __shared__ float gh[16][384];
    __shared__ int s_p[16], s_rel[16];
    if (tid < 16) {
        s_p[tid]   = g_p[step][b * TOPK + kb + tid];
        s_rel[tid] = g_r[step][b * TOPK + kb + tid];
    }
    __syncthreads();
    for (int idx = tid; idx < 16 * 128; idx += 384) {
        int n = idx >> 7, d = idx & 127;
        s_f[d * SH + n] = out[OFF_TE + ((b * 3 + (step - 1)) * 64 + s_p[n]) * 128 + d];
    }
    __syncthreads();

    const int j = tid;
    const float bj = b_hh[j];
    ull acc[8];
    ull bj2 = f2pack(bj, bj);
    #pragma unroll
    for (int m = 0; m < 8; ++m) acc[m] = bj2;
    const float* wt = g_wT[1];
    #pragma unroll 4
    for (int k = 0; k < 128; ++k) {
        float w = __ldg(&wt[k * 384 + j]);
        ull wd = f2pack(w, w);
        const ulonglong2* row = (const ulonglong2*)&s_f[k * SH];
        ulonglong2 r0 = row[0], r1 = row[1], r2 = row[2], r3 = row[3];
        acc[0] = f2fma(wd, r0.x, acc[0]); acc[1] = f2fma(wd, r0.y, acc[1]);
        acc[2] = f2fma(wd, r1.x, acc[2]); acc[3] = f2fma(wd, r1.y, acc[3]);
        acc[4] = f2fma(wd, r2.x, acc[4]); acc[5] = f2fma(wd, r2.y, acc[5]);
        acc[6] = f2fma(wd, r3.x, acc[6]); acc[7] = f2fma(wd, r3.y, acc[7]);
    }
    #pragma unroll
    for (int m = 0; m < 8; ++m) {
        float2 v = *(float2*)&acc[m];
        gh[2 * m][j]     = v.x;
        gh[2 * m + 1][j] = v.y;
    }
    __syncthreads();

    for (int idx = tid; idx < 16 * 128; idx += 384) {
        int n = idx >> 7, d = idx & 127;
        int r = s_rel[n];
        const float* gi = &g_relgi[r * 384];
        float ir = gi[d], iz = gi[128 + d], inn = gi[256 + d];
        float hr = gh[n][d], hz = gh[n][128 + d], hn = gh[n][256 + d];
        float hprev = s_f[d * SH + n];
        float rg = 1.f / (1.f + expf(-(ir + hr)));
        float z  = 1.f / (1.f + expf(-(iz + hz)));
        float nn = tanhf(inn + rg * hn);
        out[OFF_TE + ((b * 3 + step) * 64 + kb + n) * 128 + d] = (1.f - z) * nn + z * hprev;
    }
}

// ---------------- launch ------------------------------------------------------
extern "C" void kernel_launch(void* const* d_in, const int* in_sizes, int n_in,
                              void* d_out, int out_size) {
    (void)in_sizes; (void)n_in; (void)out_size;
    const int*   qh      = (const int*)d_in[0];
    const int2*  edge    = (const int2*)d_in[1];
    const int*   sup     = (const int*)d_in[2];
    const float* cosm    = (const float*)d_in[3];
    const float* rel_emb = (const float*)d_in[4];
    const float* wih     = (const float*)d_in[5];
    const float* whh     = (const float*)d_in[6];
    const float* bih     = (const float*)d_in[7];
    const float* bhh     = (const float*)d_in[8];
    float* out = (float*)d_out;

    prep_best_kernel<<<212, 256>>>(wih, whh, cosm, sup);
    relgi_kernel<<<(NRELS + 15) / 16, 384>>>(rel_emb, bih);

    expand0_kernel<<<BATCH, 128>>>(edge, qh, out);
    gru1_kernel<<<BATCH, 256>>>(bhh, out);

    expand_big_kernel<<<BATCH, 512>>>(edge, out, 1);
    gru23_kernel<<<dim3(4, BATCH), 384>>>(bhh, out, 1);

    expand_big_kernel<<<BATCH, 512>>>(edge, out, 2);
    gru23_kernel<<<dim3(4, BATCH), 384>>>(bhh, out, 2);
}

// round 3
// speedup vs baseline: 1.7734x; 1.7734x over previous
#include <cuda_runtime.h>
#include <cuda_bf16.h>
#include <math.h>

// Problem constants
#define BATCH   256
#define NEI     128
#define NRELS   5000
#define NSUP    32
#define DIM     128
#define TOPK    64
#define NCAND   8192

// d_out (float32) segment offsets (flatten+concat of the 5 reference outputs)
#define OFF_TN  0           // tree_node      [256,3,64]
#define OFF_TE  49152       // tree_emb_all   [256,3,64,128]
#define OFF_PI  6340608     // parent_index   [256,3,64]
#define OFF_PN  6389760     // parent_node    [256,3,64]
#define OFF_AR  6438912     // aim_rel_all    [256,3,64]

typedef unsigned long long ull;
typedef unsigned int u32;

// ---------------- device scratch (static: no allocation allowed) -------------
__device__ float g_best[NRELS];               // max-over-support score per relation
__device__ u32   g_rank[NRELS];               // #{r' : best[r'] > best[r]}  (strict)
__device__ float g_relgi[NRELS * 384];        // rel_emb @ W_ih^T + b_ih
__device__ float g_wT[2][128 * 384];          // [0]=W_ih^T, [1]=W_hh^T  (k-major)
__device__ int   g_e[3][BATCH * TOPK];
__device__ int   g_r[3][BATCH * TOPK];
__device__ int   g_p[3][BATCH * TOPK];

// ---------------- f32x2 packed math helpers ----------------------------------
__device__ __forceinline__ ull f2pack(float lo, float hi) {
    ull d; asm("mov.b64 %0, {%1, %2};" : "=l"(d) : "f"(lo), "f"(hi)); return d;
}
__device__ __forceinline__ ull f2fma(ull a, ull b, ull c) {
    ull d; asm("fma.rn.f32x2 %0, %1, %2, %3;" : "=l"(d) : "l"(a), "l"(b), "l"(c)); return d;
}
__device__ __forceinline__ u32 ord32(float s) {
    u32 u = __float_as_uint(s);
    return (u & 0x80000000u) ? ~u : (u | 0x80000000u);
}

// ---------------- prep: transpose weights + best[] ----------------------------
__global__ void prep_best_kernel(const float* __restrict__ wih, const float* __restrict__ whh,
                                 const float* __restrict__ cosm, const int* __restrict__ sup) {
    const int bid = blockIdx.x;
    const int tid = threadIdx.x;
    if (bid < 192) {
        int idx = bid * 256 + tid;
        if (idx < 384 * 128) {
            int j = idx / 128, k = idx % 128;
            g_wT[0][k * 384 + j] = wih[idx];
            g_wT[1][k * 384 + j] = whh[idx];
        }
    } else {
        __shared__ int ss[NSUP];
        if (tid < NSUP) ss[tid] = sup[tid];
        __syncthreads();
        int r = (bid - 192) * 256 + tid;
        if (r < NRELS) {
            float m = -3.4e38f;
            #pragma unroll
            for (int s = 0; s < NSUP; ++s)
                m = fmaxf(m, cosm[(long long)ss[s] * NRELS + r]);
            g_best[r] = m;
        }
    }
}

// ---------------- rank[r] = #{r' : best[r'] > best[r]} ------------------------
__global__ void rank_kernel() {
    __shared__ float tile[256];
    const int r = blockIdx.x * 256 + threadIdx.x;
    const float mine = (r < NRELS) ? g_best[r] : 3.4e38f;
    u32 cnt = 0;
    for (int base = 0; base < NRELS; base += 256) {
        int t = base + threadIdx.x;
        tile[threadIdx.x] = (t < NRELS) ? g_best[t] : -3.4e38f;
        __syncthreads();
        int lim = NRELS - base; if (lim > 256) lim = 256;
        #pragma unroll 8
        for (int u = 0; u < lim; ++u) cnt += (tile[u] > mine);
        __syncthreads();
    }
    if (r < NRELS) g_rank[r] = cnt;
}

// ---------------- rel_gi = rel_emb @ W_ih^T + b_ih  (FFMA2) -------------------
#define SH 20   // padded transpose row stride (floats); 20*4=80B keeps 16B align
__global__ void __launch_bounds__(384) relgi_kernel(const float* __restrict__ rel_emb,
                                                    const float* __restrict__ b_ih) {
    const int rb = blockIdx.x * 16;
    const int tid = threadIdx.x;
    __shared__ float s_f[128 * SH];   // [d][n] pair-packed along n
    for (int idx = tid; idx < 16 * 128; idx += 384) {
        int n = idx >> 7, d = idx & 127;
        int r = rb + n;
        s_f[d * SH + n] = (r < NRELS) ? rel_emb[r * 128 + d] : 0.f;
    }
    __syncthreads();
    const int j = tid;
    const float bj = b_ih[j];
    ull acc[8];
    ull bj2 = f2pack(bj, bj);
    #pragma unroll
    for (int m = 0; m < 8; ++m) acc[m] = bj2;
    const float* wt = g_wT[0];
    #pragma unroll 4
    for (int k = 0; k < 128; ++k) {
        float w = __ldg(&wt[k * 384 + j]);
        ull wd = f2pack(w, w);
        const ulonglong2* row = (const ulonglong2*)&s_f[k * SH];
        ulonglong2 r0 = row[0], r1 = row[1], r2 = row[2], r3 = row[3];
        acc[0] = f2fma(wd, r0.x, acc[0]); acc[1] = f2fma(wd, r0.y, acc[1]);
        acc[2] = f2fma(wd, r1.x, acc[2]); acc[3] = f2fma(wd, r1.y, acc[3]);
        acc[4] = f2fma(wd, r2.x, acc[4]); acc[5] = f2fma(wd, r2.y, acc[5]);
        acc[6] = f2fma(wd, r3.x, acc[6]); acc[7] = f2fma(wd, r3.y, acc[7]);
    }
    #pragma unroll
    for (int m = 0; m < 8; ++m) {
        float2 v = *(float2*)&acc[m];
        int r0i = rb + 2 * m, r1i = rb + 2 * m + 1;
        if (r0i < NRELS) g_relgi[r0i * 384 + j] = v.x;
        if (r1i < NRELS) g_relgi[r1i * 384 + j] = v.y;
    }
}

// ---------------- expand step 0: 128 candidates, rank-based top-64 ------------
__global__ void expand0_kernel(const int2* __restrict__ edge,
                               const int* __restrict__ query_head,
                               float* __restrict__ out) {
    __shared__ ull keys[128];
    __shared__ int s_ent;
    const int b = blockIdx.x;
    const int i = threadIdx.x;
    if (i == 0) s_ent = query_head[b];
    __syncthreads();
    const int ent = s_ent;
    int2 pr = __ldg(&edge[(long long)ent * NEI + i]);
    ull mykey = ((ull)ord32(g_best[pr.y]) << 32) | (u32)(127 - i);
    keys[i] = mykey;
    __syncthreads();
    int rank = 0;
    #pragma unroll 8
    for (int t = 0; t < 128; ++t) rank += (keys[t] > mykey);
    if (rank < TOPK) {
        int j = rank;
        int gidx = b * TOPK + j;
        g_e[0][gidx] = pr.x;
        g_r[0][gidx] = pr.y;
        g_p[0][gidx] = 0;
        out[OFF_TN + b * 192 + j] = (float)pr.x;
        out[OFF_PN + b * 192 + j] = (float)ent;
        out[OFF_PI + b * 192 + 128 + j] = (float)j;
    }
}

// ---------------- expand steps 1/2: bit-descent select of 64 smallest keys ----
// key = (rank[rel] << 13) | i  (26 bits, unique). Smallest 64 == XLA top-64
// with exact (value desc, index asc) semantics (equal values share a rank).
__global__ void __launch_bounds__(512) expand_big_kernel(const int2* __restrict__ edge,
                                                         float* __restrict__ out, int step) {
    __shared__ int s_cur[TOPK];
    __shared__ u32 s_wsum[16];
    __shared__ u32 s_bcast;
    __shared__ u32 wkeys[TOPK];
    __shared__ u32 s_wn;

    const int b = blockIdx.x;
    const int tid = threadIdx.x;
    const int wid = tid >> 5, lane = tid & 31;

    if (tid < TOPK) s_cur[tid] = g_e[step - 1][b * TOPK + tid];
    if (tid == 0) s_wn = 0;
    __syncthreads();

    // Phase A: build per-thread keys (16 candidates each)
    u32 myk[16];
    #pragma unroll
    for (int m = 0; m < 16; ++m) {
        int i = tid + m * 512;
        int c = i >> 7, n = i & 127;
        int2 pr = __ldg(&edge[(long long)s_cur[c] * NEI + n]);
        myk[m] = (g_rank[pr.y] << 13) | (u32)i;
    }

    // Phase B: bit-descent for K* = 64th smallest key (26-bit space).
    // Invariant: count_less(X) < 64  => K* >= X (set the bit).
    u32 K = 0;
    for (int bit = 25; bit >= 0; --bit) {
        u32 X = K | (1u << bit);
        int cnt = 0;
        #pragma unroll
        for (int m = 0; m < 16; ++m) cnt += (myk[m] < X);
        cnt = __reduce_add_sync(0xffffffffu, (u32)cnt);
        if (lane == 0) s_wsum[wid] = cnt;
        __syncthreads();
        if (tid < 32) {
            u32 v = (tid < 16) ? s_wsum[tid] : 0u;
            v = __reduce_add_sync(0xffffffffu, v);
            if (tid == 0) s_bcast = v;
        }
        __syncthreads();
        if (s_bcast < TOPK) K = X;
    }

    // Phase C: compact the exactly-64 winners (keys <= K; keys are unique)
    #pragma unroll
    for (int m = 0; m < 16; ++m) {
        if (myk[m] <= K) {
            u32 p = atomicAdd(&s_wn, 1u);
            wkeys[p] = myk[m];
        }
    }
    __syncthreads();

    // Phase D: rank winners (key asc == value desc, index asc) and emit
    if (tid < TOPK) {
        u32 my = wkeys[tid];
        int rank = 0;
        #pragma unroll 8
        for (int t = 0; t < TOPK; ++t) rank += (wkeys[t] < my);
        int i = my & (NCAND - 1);
        int c = i >> 7, n = i & 127;
        int ent = s_cur[c];
        int2 pr = __ldg(&edge[(long long)ent * NEI + n]);
        int j = rank;
        int gidx = b * TOPK + j;
        g_e[step][gidx] = pr.x;
        g_r[step][gidx] = pr.y;
        g_p[step][gidx] = c;
        out[OFF_TN + b * 192 + step * 64 + j] = (float)pr.x;
        if (step == 1) {
            out[OFF_PI + b * 192 + j]       = (float)c;
            out[OFF_PN + b * 192 + 64 + j]  = (float)g_e[0][b * TOPK + c];
            out[OFF_AR + b * 192 + j]       = (float)g_r[0][b * TOPK + c];
        } else {
            out[OFF_PI + b * 192 + 64 + j]  = (float)c;
            out[OFF_PN + b * 192 + 128 + j] = (float)g_e[1][b * TOPK + c];
            out[OFF_AR + b * 192 + 64 + j]  = (float)g_r[1][b * TOPK + c];
            out[OFF_AR + b * 192 + 128 + j] = (float)pr.y;
        }
    }
}

// ---------------- GRU step 1 (h = 0 => gh = b_hh) — flat, full occupancy -----
__global__ void gru1_kernel(const float* __restrict__ b_hh, float* __restrict__ out) {
    const int idx = blockIdx.x * blockDim.x + threadIdx.x;   // [0, 256*64*128)
    const int d = idx & 127;
    const int k = (idx >> 7) & 63;
    const int b = idx >> 13;
    const int r = g_r[0][b * TOPK + k];
    const float* gi = &g_relgi[r * 384];
    float hr = b_hh[d], hz = b_hh[128 + d], hn = b_hh[256 + d];
    float rg = 1.f / (1.f + expf(-(gi[d] + hr)));
    float z  = 1.f / (1.f + expf(-(gi[128 + d] + hz)));
    float nn = tanhf(gi[256 + d] + rg * hn);
    out[OFF_TE + idx] = (1.f - z) * nn;   // idx == ((b*3+0)*64+k)*128+d layout offset per b: b*3*64*128... 
}

// NOTE: tree_emb layout is [b][3][64][128]; step-0 slice for batch b starts at
// b*3*8192, so flat idx must be remapped. Correct store below.
__global__ void gru1_fix_kernel(const float* __restrict__ b_hh, float* __restrict__ out) {
    const int idx = blockIdx.x * blockDim.x + threadIdx.x;
    const int d = idx & 127;
    const int k = (idx >> 7) & 63;
    const int b = idx >> 13;
    const int r = g_r[0][b * TOPK + k];
    const float* gi = &g_relgi[r * 384];
    float hr = b_hh[d], hz = b_hh[128 + d], hn = b_hh[256 + d];
    float rg = 1.f / (1.f + expf(-(gi[d] + hr)));
    float z  = 1.f / (1.f + expf(-(gi[128 + d] + hz)));
    float nn = tanhf(gi[256 + d] + rg * hn);
    out[OFF_TE + ((b * 3 + 0) * 64 + k) * 128 + d] = (1.f - z) * nn;
}

// ---------------- GRU steps 2/3: gh = h_parent @ W_hh^T + b_hh  (FFMA2) ------
__global__ void __launch_bounds__(384) gru23_kernel(const float* __restrict__ b_hh,
                                                    float* __restrict__ out, int step) {
    const int b = blockIdx.y;
    const int kb = blockIdx.x * 16;
    const int tid = threadIdx.x;
    __shared__ float s_f[128 * SH];   // h_parent transposed: s_f[d*SH+n] = h[n][d]
    __shared__ float gh[16][384];
    __shared__ int s_p[16], s_rel[16];
    if (tid < 16) {
        s_p[tid]   = g_p[step][b * TOPK + kb + tid];
        s_rel[tid] = g_r[step][b * TOPK + kb + tid];
    }
    __syncthreads();
    for (int idx = tid; idx < 16 * 128; idx += 384) {
        int n = idx >> 7, d = idx & 127;
        s_f[d * SH + n] = out[OFF_TE + ((b * 3 + (step - 1)) * 64 + s_p[n]) * 128 + d];
    }
    __syncthreads();

    const int j = tid;
    const float bj = b_hh[j];
    ull acc[8];
    ull bj2 = f2pack(bj, bj);
    #pragma unroll
    for (int m = 0; m < 8; ++m) acc[m] = bj2;
    const float* wt = g_wT[1];
    #pragma unroll 4
    for (int k = 0; k < 128; ++k) {
        float w = __ldg(&wt[k * 384 + j]);
        ull wd = f2pack(w, w);
        const ulonglong2* row = (const ulonglong2*)&s_f[k * SH];
        ulonglong2 r0 = row[0], r1 = row[1], r2 = row[2], r3 = row[3];
        acc[0] = f2fma(wd, r0.x, acc[0]); acc[1] = f2fma(wd, r0.y, acc[1]);
        acc[2] = f2fma(wd, r1.x, acc[2]); acc[3] = f2fma(wd, r1.y, acc[3]);
        acc[4] = f2fma(wd, r2.x, acc[4]); acc[5] = f2fma(wd, r2.y, acc[5]);
        acc[6] = f2fma(wd, r3.x, acc[6]); acc[7] = f2fma(wd, r3.y, acc[7]);
    }
    #pragma unroll
    for (int m = 0; m < 8; ++m) {
        float2 v = *(float2*)&acc[m];
        gh[2 * m][j]     = v.x;
        gh[2 * m + 1][j] = v.y;
    }
    __syncthreads();

    for (int idx = tid; idx < 16 * 128; idx += 384) {
        int n = idx >> 7, d = idx & 127;
        int r = s_rel[n];
        const float* gi = &g_relgi[r * 384];
        float ir = gi[d], iz = gi[128 + d], inn = gi[256 + d];
        float hr = gh[n][d], hz = gh[n][128 + d], hn = gh[n][256 + d];
        float hprev = s_f[d * SH + n];
        float rg = 1.f / (1.f + expf(-(ir + hr)));
        float z  = 1.f / (1.f + expf(-(iz + hz)));
        float nn = tanhf(inn + rg * hn);
        out[OFF_TE + ((b * 3 + step) * 64 + kb + n) * 128 + d] = (1.f - z) * nn + z * hprev;
    }
}

// ---------------- launch ------------------------------------------------------
extern "C" void kernel_launch(void* const* d_in, const int* in_sizes, int n_in,
                              void* d_out, int out_size) {
    (void)in_sizes; (void)n_in; (void)out_size;
    const int*   qh      = (const int*)d_in[0];
    const int2*  edge    = (const int2*)d_in[1];
    const int*   sup     = (const int*)d_in[2];
    const float* cosm    = (const float*)d_in[3];
    const float* rel_emb = (const float*)d_in[4];
    const float* wih     = (const float*)d_in[5];
    const float* whh     = (const float*)d_in[6];
    const float* bih     = (const float*)d_in[7];
    const float* bhh     = (const float*)d_in[8];
    float* out = (float*)d_out;

    prep_best_kernel<<<212, 256>>>(wih, whh, cosm, sup);
    rank_kernel<<<(NRELS + 255) / 256, 256>>>();
    relgi_kernel<<<(NRELS + 15) / 16, 384>>>(rel_emb, bih);

    expand0_kernel<<<BATCH, 128>>>(edge, qh, out);
    gru1_fix_kernel<<<(BATCH * TOPK * DIM) / 256, 256>>>(bhh, out);

    expand_big_kernel<<<BATCH, 512>>>(edge, out, 1);
    gru23_kernel<<<dim3(4, BATCH), 384>>>(bhh, out, 1);

    expand_big_kernel<<<BATCH, 512>>>(edge, out, 2);
    gru23_kernel<<<dim3(4, BATCH), 384>>>(bhh, out, 2);
}

// round 4
// speedup vs baseline: 1.9024x; 1.0727x over previous
#include <cuda_runtime.h>
#include <cuda_bf16.h>
#include <math.h>

// Problem constants
#define BATCH   256
#define NEI     128
#define NRELS   5000
#define NSUP    32
#define DIM     128
#define TOPK    64
#define NCAND   8192

// d_out (float32) segment offsets (flatten+concat of the 5 reference outputs)
#define OFF_TN  0           // tree_node      [256,3,64]
#define OFF_TE  49152       // tree_emb_all   [256,3,64,128]
#define OFF_PI  6340608     // parent_index   [256,3,64]
#define OFF_PN  6389760     // parent_node    [256,3,64]
#define OFF_AR  6438912     // aim_rel_all    [256,3,64]

typedef unsigned long long ull;
typedef unsigned int u32;

// ---------------- device scratch (static: no allocation allowed) -------------
__device__ float g_best[NRELS];               // max-over-support score per relation
__device__ u32   g_rank[NRELS];               // #{r' : best[r'] > best[r]}  (strict)
__device__ float g_relgi[NRELS * 384];        // rel_emb @ W_ih^T + b_ih
__device__ float g_wT[2][128 * 384];          // [0]=W_ih^T, [1]=W_hh^T  (k-major)
__device__ int   g_e[3][BATCH * TOPK];
__device__ int   g_r[3][BATCH * TOPK];
__device__ int   g_p[3][BATCH * TOPK];

// ---------------- f32x2 packed math helpers ----------------------------------
__device__ __forceinline__ ull f2pack(float lo, float hi) {
    ull d; asm("mov.b64 %0, {%1, %2};" : "=l"(d) : "f"(lo), "f"(hi)); return d;
}
__device__ __forceinline__ ull f2fma(ull a, ull b, ull c) {
    ull d; asm("fma.rn.f32x2 %0, %1, %2, %3;" : "=l"(d) : "l"(a), "l"(b), "l"(c)); return d;
}
__device__ __forceinline__ u32 ord32(float s) {
    u32 u = __float_as_uint(s);
    return (u & 0x80000000u) ? ~u : (u | 0x80000000u);
}

// ---------------- chain A prep: transpose weights -----------------------------
__global__ void prep_w_kernel(const float* __restrict__ wih, const float* __restrict__ whh) {
    int idx = blockIdx.x * 256 + threadIdx.x;
    if (idx < 384 * 128) {
        int j = idx / 128, k = idx % 128;
        g_wT[0][k * 384 + j] = wih[idx];
        g_wT[1][k * 384 + j] = whh[idx];
    }
}

// ---------------- chain B prep: best[r] ---------------------------------------
__global__ void best_kernel(const float* __restrict__ cosm, const int* __restrict__ sup) {
    __shared__ int ss[NSUP];
    if (threadIdx.x < NSUP) ss[threadIdx.x] = sup[threadIdx.x];
    __syncthreads();
    int r = blockIdx.x * 256 + threadIdx.x;
    if (r < NRELS) {
        float m = -3.4e38f;
        #pragma unroll
        for (int s = 0; s < NSUP; ++s)
            m = fmaxf(m, cosm[(long long)ss[s] * NRELS + r]);
        g_best[r] = m;
    }
}

// ---------------- rank[r] = #{r' : best[r'] > best[r]} ------------------------
__global__ void rank_kernel() {
    __shared__ float tile[256];
    const int r = blockIdx.x * 256 + threadIdx.x;
    const float mine = (r < NRELS) ? g_best[r] : 3.4e38f;
    u32 cnt = 0;
    for (int base = 0; base < NRELS; base += 256) {
        int t = base + threadIdx.x;
        tile[threadIdx.x] = (t < NRELS) ? g_best[t] : -3.4e38f;
        __syncthreads();
        int lim = NRELS - base; if (lim > 256) lim = 256;
        #pragma unroll 8
        for (int u = 0; u < lim; ++u) cnt += (tile[u] > mine);
        __syncthreads();
    }
    if (r < NRELS) g_rank[r] = cnt;
}

// ---------------- rel_gi = rel_emb @ W_ih^T + b_ih  (FFMA2) -------------------
#define SH 20   // padded transpose row stride (floats); 20*4=80B keeps 16B align
__global__ void __launch_bounds__(384) relgi_kernel(const float* __restrict__ rel_emb,
                                                    const float* __restrict__ b_ih) {
    const int rb = blockIdx.x * 16;
    const int tid = threadIdx.x;
    __shared__ float s_f[128 * SH];   // [d][n] pair-packed along n
    for (int idx = tid; idx < 16 * 128; idx += 384) {
        int n = idx >> 7, d = idx & 127;
        int r = rb + n;
        s_f[d * SH + n] = (r < NRELS) ? rel_emb[r * 128 + d] : 0.f;
    }
    __syncthreads();
    const int j = tid;
    const float bj = b_ih[j];
    ull acc[8];
    ull bj2 = f2pack(bj, bj);
    #pragma unroll
    for (int m = 0; m < 8; ++m) acc[m] = bj2;
    const float* wt = g_wT[0];
    #pragma unroll 4
    for (int k = 0; k < 128; ++k) {
        float w = __ldg(&wt[k * 384 + j]);
        ull wd = f2pack(w, w);
        const ulonglong2* row = (const ulonglong2*)&s_f[k * SH];
        ulonglong2 r0 = row[0], r1 = row[1], r2 = row[2], r3 = row[3];
        acc[0] = f2fma(wd, r0.x, acc[0]); acc[1] = f2fma(wd, r0.y, acc[1]);
        acc[2] = f2fma(wd, r1.x, acc[2]); acc[3] = f2fma(wd, r1.y, acc[3]);
        acc[4] = f2fma(wd, r2.x, acc[4]); acc[5] = f2fma(wd, r2.y, acc[5]);
        acc[6] = f2fma(wd, r3.x, acc[6]); acc[7] = f2fma(wd, r3.y, acc[7]);
    }
    #pragma unroll
    for (int m = 0; m < 8; ++m) {
        float2 v = *(float2*)&acc[m];
        int r0i = rb + 2 * m, r1i = rb + 2 * m + 1;
        if (r0i < NRELS) g_relgi[r0i * 384 + j] = v.x;
        if (r1i < NRELS) g_relgi[r1i * 384 + j] = v.y;
    }
}

// ---------------- expand step 0: 128 candidates, rank-based top-64 ------------
__global__ void expand0_kernel(const int2* __restrict__ edge,
                               const int* __restrict__ query_head,
                               float* __restrict__ out) {
    __shared__ ull keys[128];
    __shared__ int s_ent;
    const int b = blockIdx.x;
    const int i = threadIdx.x;
    if (i == 0) s_ent = query_head[b];
    __syncthreads();
    const int ent = s_ent;
    int2 pr = __ldg(&edge[(long long)ent * NEI + i]);
    ull mykey = ((ull)ord32(g_best[pr.y]) << 32) | (u32)(127 - i);
    keys[i] = mykey;
    __syncthreads();
    int rank = 0;
    #pragma unroll 8
    for (int t = 0; t < 128; ++t) rank += (keys[t] > mykey);
    if (rank < TOPK) {
        int j = rank;
        int gidx = b * TOPK + j;
        g_e[0][gidx] = pr.x;
        g_r[0][gidx] = pr.y;
        g_p[0][gidx] = 0;
        out[OFF_TN + b * 192 + j] = (float)pr.x;
        out[OFF_PN + b * 192 + j] = (float)ent;
        out[OFF_PI + b * 192 + 128 + j] = (float)j;
    }
}

// ---------------- expand steps 1/2: radix-4 descent, 64 smallest keys ---------
// key = (rank[rel] << 13) | i  (26 bits, unique). Smallest 64 == XLA top-64.
__global__ void __launch_bounds__(512) expand_big_kernel(const int2* __restrict__ edge,
                                                         float* __restrict__ out, int step) {
    __shared__ int s_cur[TOPK];
    __shared__ u32 s_p13[16], s_q13[16];
    __shared__ u32 s_bp, s_bq;
    __shared__ u32 wkeys[TOPK];
    __shared__ u32 s_wn;

    const int b = blockIdx.x;
    const int tid = threadIdx.x;
    const int wid = tid >> 5, lane = tid & 31;

    if (tid < TOPK) s_cur[tid] = g_e[step - 1][b * TOPK + tid];
    if (tid == 0) s_wn = 0;
    __syncthreads();

    // Phase A: build per-thread keys (16 candidates each)
    u32 myk[16];
    #pragma unroll
    for (int m = 0; m < 16; ++m) {
        int i = tid + m * 512;
        int c = i >> 7, n = i & 127;
        int2 pr = __ldg(&edge[(long long)s_cur[c] * NEI + n]);
        myk[m] = (g_rank[pr.y] << 13) | (u32)i;
    }

    // Phase B: radix-4 descent for K* = 64th smallest key (26-bit space).
    // P(X) := count_less(X) < 64  =>  K* >= X.
    u32 K = 0;
    #pragma unroll 1
    for (int shift = 24; shift >= 0; shift -= 2) {
        u32 X1 = K | (1u << shift), X2 = K | (2u << shift), X3 = K | (3u << shift);
        u32 c1 = 0, c2 = 0, c3 = 0;
        #pragma unroll
        for (int m = 0; m < 16; ++m) {
            u32 k0 = myk[m];
            c1 += (k0 < X1); c2 += (k0 < X2); c3 += (k0 < X3);
        }
        u32 p = c1 | (c2 << 16);   // each field sums to <= 8192 block-wide
        u32 q = c3;
        p = __reduce_add_sync(0xffffffffu, p);
        q = __reduce_add_sync(0xffffffffu, q);
        if (lane == 0) { s_p13[wid] = p; s_q13[wid] = q; }
        __syncthreads();
        if (tid < 32) {
            u32 vp = (tid < 16) ? s_p13[tid] : 0u;
            u32 vq = (tid < 16) ? s_q13[tid] : 0u;
            vp = __reduce_add_sync(0xffffffffu, vp);
            vq = __reduce_add_sync(0xffffffffu, vq);
            if (tid == 0) { s_bp = vp; s_bq = vq; }
        }
        __syncthreads();
        u32 n1 = s_bp & 0xffffu, n2 = s_bp >> 16, n3 = s_bq;
        u32 t = (n1 < TOPK) ? ((n2 < TOPK) ? ((n3 < TOPK) ? 3u : 2u) : 1u) : 0u;
        K |= t << shift;
        __syncthreads();
    }

    // Phase C: compact the exactly-64 winners (keys <= K; keys are unique)
    #pragma unroll
    for (int m = 0; m < 16; ++m) {
        if (myk[m] <= K) {
            u32 p = atomicAdd(&s_wn, 1u);
            wkeys[p] = myk[m];
        }
    }
    __syncthreads();

    // Phase D: rank winners (key asc == value desc, index asc) and emit
    if (tid < TOPK) {
        u32 my = wkeys[tid];
        int rank = 0;
        #pragma unroll 8
        for (int t = 0; t < TOPK; ++t) rank += (wkeys[t] < my);
        int i = my & (NCAND - 1);
        int c = i >> 7, n = i & 127;
        int ent = s_cur[c];
        int2 pr = __ldg(&edge[(long long)ent * NEI + n]);
        int j = rank;
        int gidx = b * TOPK + j;
        g_e[step][gidx] = pr.x;
        g_r[step][gidx] = pr.y;
        g_p[step][gidx] = c;
        out[OFF_TN + b * 192 + step * 64 + j] = (float)pr.x;
        if (step == 1) {
            out[OFF_PI + b * 192 + j]       = (float)c;
            out[OFF_PN + b * 192 + 64 + j]  = (float)g_e[0][b * TOPK + c];
            out[OFF_AR + b * 192 + j]       = (float)g_r[0][b * TOPK + c];
        } else {
            out[OFF_PI + b * 192 + 64 + j]  = (float)c;
            out[OFF_PN + b * 192 + 128 + j] = (float)g_e[1][b * TOPK + c];
            out[OFF_AR + b * 192 + 64 + j]  = (float)g_r[1][b * TOPK + c];
            out[OFF_AR + b * 192 + 128 + j] = (float)pr.y;
        }
    }
}

// ---------------- GRU step 1 (h = 0 => gh = b_hh) — flat, full occupancy -----
__global__ void gru1_kernel(const float* __restrict__ b_hh, float* __restrict__ out) {
    const int idx = blockIdx.x * blockDim.x + threadIdx.x;
    const int d = idx & 127;
    const int k = (idx >> 7) & 63;
    const int b = idx >> 13;
    const int r = g_r[0][b * TOPK + k];
    const float* gi = &g_relgi[r * 384];
    float hr = b_hh[d], hz = b_hh[128 + d], hn = b_hh[256 + d];
    float rg = 1.f / (1.f + expf(-(gi[d] + hr)));
    float z  = 1.f / (1.f + expf(-(gi[128 + d] + hz)));
    float nn = tanhf(gi[256 + d] + rg * hn);
    out[OFF_TE + ((b * 3 + 0) * 64 + k) * 128 + d] = (1.f - z) * nn;
}

// ---------------- GRU steps 2/3: gh = h_parent @ W_hh^T + b_hh  (FFMA2) ------
__global__ void __launch_bounds__(384) gru23_kernel(const float* __restrict__ b_hh,
                                                    float* __restrict__ out, int step) {
    const int b = blockIdx.y;
    const int kb = blockIdx.x * 16;
    const int tid = threadIdx.x;
    __shared__ float s_f[128 * SH];   // h_parent transposed: s_f[d*SH+n] = h[n][d]
    __shared__ float gh[16][384];
    __shared__ int s_p[16], s_rel[16];
    if (tid < 16) {
        s_p[tid]   = g_p[step][b * TOPK + kb + tid];
        s_rel[tid] = g_r[step][b * TOPK + kb + tid];
    }
    __syncthreads();
    for (int idx = tid; idx < 16 * 128; idx += 384) {
        int n = idx >> 7, d = idx & 127;
        s_f[d * SH + n] = out[OFF_TE + ((b * 3 + (step - 1)) * 64 + s_p[n]) * 128 + d];
    }
    __syncthreads();

    const int j = tid;
    const float bj = b_hh[j];
    ull acc[8];
    ull bj2 = f2pack(bj, bj);
    #pragma unroll
    for (int m = 0; m < 8; ++m) acc[m] = bj2;
    const float* wt = g_wT[1];
    #pragma unroll 4
    for (int k = 0; k < 128; ++k) {
        float w = __ldg(&wt[k * 384 + j]);
        ull wd = f2pack(w, w);
        const ulonglong2* row = (const ulonglong2*)&s_f[k * SH];
        ulonglong2 r0 = row[0], r1 = row[1], r2 = row[2], r3 = row[3];
        acc[0] = f2fma(wd, r0.x, acc[0]); acc[1] = f2fma(wd, r0.y, acc[1]);
        acc[2] = f2fma(wd, r1.x, acc[2]); acc[3] = f2fma(wd, r1.y, acc[3]);
        acc[4] = f2fma(wd, r2.x, acc[4]); acc[5] = f2fma(wd, r2.y, acc[5]);
        acc[6] = f2fma(wd, r3.x, acc[6]); acc[7] = f2fma(wd, r3.y, acc[7]);
    }
    #pragma unroll
    for (int m = 0; m < 8; ++m) {
        float2 v = *(float2*)&acc[m];
        gh[2 * m][j]     = v.x;
        gh[2 * m + 1][j] = v.y;
    }
    __syncthreads();

    for (int idx = tid; idx < 16 * 128; idx += 384) {
        int n = idx >> 7, d = idx & 127;
        int r = s_rel[n];
        const float* gi = &g_relgi[r * 384];
        float ir = gi[d], iz = gi[128 + d], inn = gi[256 + d];
        float hr = gh[n][d], hz = gh[n][128 + d], hn = gh[n][256 + d];
        float hprev = s_f[d * SH + n];
        float rg = 1.f / (1.f + expf(-(ir + hr)));
        float z  = 1.f / (1.f + expf(-(iz + hz)));
        float nn = tanhf(inn + rg * hn);
        out[OFF_TE + ((b * 3 + step) * 64 + kb + n) * 128 + d] = (1.f - z) * nn + z * hprev;
    }
}

// ---------------- launch: two-stream forked capture ---------------------------
extern "C" void kernel_launch(void* const* d_in, const int* in_sizes, int n_in,
                              void* d_out, int out_size) {
    (void)in_sizes; (void)n_in; (void)out_size;
    const int*   qh      = (const int*)d_in[0];
    const int2*  edge    = (const int2*)d_in[1];
    const int*   sup     = (const int*)d_in[2];
    const float* cosm    = (const float*)d_in[3];
    const float* rel_emb = (const float*)d_in[4];
    const float* wih     = (const float*)d_in[5];
    const float* whh     = (const float*)d_in[6];
    const float* bih     = (const float*)d_in[7];
    const float* bhh     = (const float*)d_in[8];
    float* out = (float*)d_out;

    static cudaStream_t sB = nullptr;
    static cudaEvent_t evFork, evE0, evX1, evX2;
    if (!sB) {
        cudaStreamCreateWithFlags(&sB, cudaStreamNonBlocking);
        cudaEventCreateWithFlags(&evFork, cudaEventDisableTiming);
        cudaEventCreateWithFlags(&evE0, cudaEventDisableTiming);
        cudaEventCreateWithFlags(&evX1, cudaEventDisableTiming);
        cudaEventCreateWithFlags(&evX2, cudaEventDisableTiming);
    }

    // fork side chain B off the origin (captured) stream
    cudaEventRecord(evFork, 0);
    cudaStreamWaitEvent(sB, evFork, 0);

    // ---- chain B (side stream): best -> expand0 -> rank -> xbig1 -> xbig2 ----
    best_kernel<<<(NRELS + 255) / 256, 256, 0, sB>>>(cosm, sup);
    expand0_kernel<<<BATCH, 128, 0, sB>>>(edge, qh, out);
    cudaEventRecord(evE0, sB);
    rank_kernel<<<(NRELS + 255) / 256, 256, 0, sB>>>();
    expand_big_kernel<<<BATCH, 512, 0, sB>>>(edge, out, 1);
    cudaEventRecord(evX1, sB);
    expand_big_kernel<<<BATCH, 512, 0, sB>>>(edge, out, 2);
    cudaEventRecord(evX2, sB);

    // ---- chain A (origin stream): prep_w -> relgi -> gru1 -> gru23 x2 --------
    prep_w_kernel<<<192, 256>>>(wih, whh);
    relgi_kernel<<<(NRELS + 15) / 16, 384>>>(rel_emb, bih);
    cudaStreamWaitEvent(0, evE0, 0);
    gru1_kernel<<<(BATCH * TOPK * DIM) / 256, 256>>>(bhh, out);
    cudaStreamWaitEvent(0, evX1, 0);
    gru23_kernel<<<dim3(4, BATCH), 384>>>(bhh, out, 1);
    cudaStreamWaitEvent(0, evX2, 0);
    gru23_kernel<<<dim3(4, BATCH), 384>>>(bhh, out, 2);
}